// round 1
// baseline (speedup 1.0000x reference)
#include <cuda_runtime.h>

#define S_LEN  2048
#define BATCH  2
#define HID    1024
#define NHEAD  16
#define DHEAD  64
#define MHEADS 32            // BATCH * NHEAD
#define K_DIM  1024
#define N_DIM  3072
#define M_DIM  4096          // S_LEN * BATCH

// Scratch (allocation-free rule: __device__ globals). 48 MB total.
__device__ float g_Q[(size_t)MHEADS * S_LEN * DHEAD];
__device__ float g_K[(size_t)MHEADS * S_LEN * DHEAD];
__device__ float g_V[(size_t)MHEADS * S_LEN * DHEAD];

// ---------------------------------------------------------------------------
// Kernel 1: QKV projection C[m][n] = sum_k A[m][k]*W[n][k] + bias[n],
// scattered directly into per-head Q/K/V layout [mh][s][d].
// Block tile 128x128, K-chunk 16, 256 threads, 8x8 per thread.
// ---------------------------------------------------------------------------
__global__ __launch_bounds__(256) void qkv_gemm_kernel(
    const float* __restrict__ A,      // [4096][1024] (s*B+b major)
    const float* __restrict__ W,      // [3072][1024]
    const float* __restrict__ bias)   // [3072]
{
    __shared__ float As[16][128];     // As[k][m]
    __shared__ float Bs[16][128];     // Bs[k][n]

    const int tid = threadIdx.x;
    const int tx  = tid & 15;         // n-tile index
    const int ty  = tid >> 4;         // m-tile index
    const int m0  = blockIdx.y * 128;
    const int n0  = blockIdx.x * 128;

    float acc[8][8];
    #pragma unroll
    for (int i = 0; i < 8; ++i)
        #pragma unroll
        for (int j = 0; j < 8; ++j) acc[i][j] = 0.f;

    const int lr = tid >> 2;          // 0..63 row
    const int lk = (tid & 3) << 2;    // 0,4,8,12 k-offset

    for (int k0 = 0; k0 < K_DIM; k0 += 16) {
        #pragma unroll
        for (int p = 0; p < 2; ++p) {
            int row = lr + p * 64;
            float4 va = *(const float4*)(A + (size_t)(m0 + row) * K_DIM + k0 + lk);
            As[lk + 0][row] = va.x; As[lk + 1][row] = va.y;
            As[lk + 2][row] = va.z; As[lk + 3][row] = va.w;
            float4 vb = *(const float4*)(W + (size_t)(n0 + row) * K_DIM + k0 + lk);
            Bs[lk + 0][row] = vb.x; Bs[lk + 1][row] = vb.y;
            Bs[lk + 2][row] = vb.z; Bs[lk + 3][row] = vb.w;
        }
        __syncthreads();

        #pragma unroll
        for (int k = 0; k < 16; ++k) {
            float a[8], b[8];
            *(float4*)&a[0] = *(const float4*)&As[k][ty * 8];
            *(float4*)&a[4] = *(const float4*)&As[k][ty * 8 + 4];
            *(float4*)&b[0] = *(const float4*)&Bs[k][tx * 8];
            *(float4*)&b[4] = *(const float4*)&Bs[k][tx * 8 + 4];
            #pragma unroll
            for (int i = 0; i < 8; ++i)
                #pragma unroll
                for (int j = 0; j < 8; ++j)
                    acc[i][j] = fmaf(a[i], b[j], acc[i][j]);
        }
        __syncthreads();
    }

    // Epilogue: bias + scatter into [mh = b*16+head][s][d] for q/k/v.
    #pragma unroll
    for (int j = 0; j < 8; ++j) {
        int n    = n0 + tx * 8 + j;
        float bj = bias[n];
        int head = n / 192;
        int w    = n - head * 192;      // 0..191
        int sel  = w >> 6;              // 0=q 1=k 2=v
        int d    = w & 63;
        float* dst = (sel == 0) ? g_Q : ((sel == 1) ? g_K : g_V);
        #pragma unroll
        for (int i = 0; i < 8; ++i) {
            int m  = m0 + ty * 8 + i;   // = s*BATCH + b
            int s  = m >> 1;
            int b  = m & 1;
            int mh = (b << 4) + head;
            dst[((size_t)mh * S_LEN + s) * DHEAD + d] = acc[i][j] + bj;
        }
    }
}

// ---------------------------------------------------------------------------
// Kernel 2: attention. One block = (head m, 64-row Q tile). Loops over 32
// K/V tiles of 64 rows. Per tile: S = (sq+sk-2 QK^T)*(-1/16) -> write scores
// -> P = exp(S) -> ctx += P @ V. 256 threads, 4x4 microtiles.
// ---------------------------------------------------------------------------
__global__ __launch_bounds__(256) void attn_kernel(
    float* __restrict__ ctx_out,      // [S][B][H]
    float* __restrict__ score_out)    // [MHEADS][S][S]
{
    extern __shared__ float smem[];
    float* Qt = smem;                 // [64][68]  Qt[d][i]
    float* Kt = smem + 64 * 68;       // [64][68]  Kt[d][j]
    float* Vs = smem + 2 * 64 * 68;   // [64][68]  Vs[j][d]
    float* Pt = smem + 3 * 64 * 68;   // [64][68]  Pt[j][i]
    float* sq = smem + 4 * 64 * 68;   // [64]
    float* sk = sq + 64;              // [64]

    const int tid = threadIdx.x;
    const int tx  = tid & 15;
    const int ty  = tid >> 4;
    const int m   = blockIdx.y;       // head 0..31
    const int q0  = blockIdx.x * 64;

    // Load Q tile transposed: Qt[d][i]
    const float* Qg = g_Q + ((size_t)m * S_LEN + q0) * DHEAD;
    {
        int r  = tid >> 4;            // 0..15
        int dq = (tid & 15) * 4;
        #pragma unroll
        for (int p = 0; p < 4; ++p) {
            int row = r + p * 16;
            float4 v = *(const float4*)(Qg + row * 64 + dq);
            Qt[(dq + 0) * 68 + row] = v.x;
            Qt[(dq + 1) * 68 + row] = v.y;
            Qt[(dq + 2) * 68 + row] = v.z;
            Qt[(dq + 3) * 68 + row] = v.w;
        }
    }
    __syncthreads();
    if (tid < 64) {
        float s = 0.f;
        #pragma unroll
        for (int d = 0; d < 64; ++d) { float q = Qt[d * 68 + tid]; s = fmaf(q, q, s); }
        sq[tid] = s;
    }

    float ctx[4][4];
    #pragma unroll
    for (int i = 0; i < 4; ++i)
        #pragma unroll
        for (int c = 0; c < 4; ++c) ctx[i][c] = 0.f;

    for (int t0 = 0; t0 < S_LEN; t0 += 64) {
        __syncthreads();   // previous-iteration readers done (also orders sq)

        const float* Kg = g_K + ((size_t)m * S_LEN + t0) * DHEAD;
        const float* Vg = g_V + ((size_t)m * S_LEN + t0) * DHEAD;
        {
            int r  = tid >> 4;
            int dq = (tid & 15) * 4;
            #pragma unroll
            for (int p = 0; p < 4; ++p) {
                int row = r + p * 16;
                float4 v = *(const float4*)(Kg + row * 64 + dq);
                Kt[(dq + 0) * 68 + row] = v.x;
                Kt[(dq + 1) * 68 + row] = v.y;
                Kt[(dq + 2) * 68 + row] = v.z;
                Kt[(dq + 3) * 68 + row] = v.w;
                float4 w = *(const float4*)(Vg + row * 64 + dq);
                *(float4*)(Vs + row * 68 + dq) = w;
            }
        }
        __syncthreads();
        if (tid < 64) {
            float s = 0.f;
            #pragma unroll
            for (int d = 0; d < 64; ++d) { float k = Kt[d * 68 + tid]; s = fmaf(k, k, s); }
            sk[tid] = s;
        }
        __syncthreads();

        // GEMM1: acc[i][j] = sum_d Q[q0+ty*4+i][d] * K[t0+tx*4+j][d]
        float acc[4][4];
        #pragma unroll
        for (int i = 0; i < 4; ++i)
            #pragma unroll
            for (int j = 0; j < 4; ++j) acc[i][j] = 0.f;

        #pragma unroll 8
        for (int d = 0; d < 64; ++d) {
            float4 qv = *(const float4*)(Qt + d * 68 + ty * 4);
            float4 kv = *(const float4*)(Kt + d * 68 + tx * 4);
            float qa[4] = {qv.x, qv.y, qv.z, qv.w};
            float ka[4] = {kv.x, kv.y, kv.z, kv.w};
            #pragma unroll
            for (int i = 0; i < 4; ++i)
                #pragma unroll
                for (int j = 0; j < 4; ++j)
                    acc[i][j] = fmaf(qa[i], ka[j], acc[i][j]);
        }

        // Scores + exp + write
        float sqr[4], skr[4];
        #pragma unroll
        for (int i = 0; i < 4; ++i) sqr[i] = sq[ty * 4 + i];
        #pragma unroll
        for (int j = 0; j < 4; ++j) skr[j] = sk[tx * 4 + j];

        #pragma unroll
        for (int i = 0; i < 4; ++i) {
            float4 sc;
            sc.x = (sqr[i] + skr[0] - 2.f * acc[i][0]) * -0.0625f;
            sc.y = (sqr[i] + skr[1] - 2.f * acc[i][1]) * -0.0625f;
            sc.z = (sqr[i] + skr[2] - 2.f * acc[i][2]) * -0.0625f;
            sc.w = (sqr[i] + skr[3] - 2.f * acc[i][3]) * -0.0625f;
            *(float4*)(score_out + ((size_t)m * S_LEN + q0 + ty * 4 + i) * S_LEN
                                 + t0 + tx * 4) = sc;
            Pt[(tx * 4 + 0) * 68 + ty * 4 + i] = __expf(sc.x);
            Pt[(tx * 4 + 1) * 68 + ty * 4 + i] = __expf(sc.y);
            Pt[(tx * 4 + 2) * 68 + ty * 4 + i] = __expf(sc.z);
            Pt[(tx * 4 + 3) * 68 + ty * 4 + i] = __expf(sc.w);
        }
        __syncthreads();

        // GEMM2: ctx[i][c] += sum_j P[q-row i][j] * V[j][d-col c]
        #pragma unroll 8
        for (int j = 0; j < 64; ++j) {
            float4 pv = *(const float4*)(Pt + j * 68 + ty * 4);
            float4 vv = *(const float4*)(Vs + j * 68 + tx * 4);
            float pa[4] = {pv.x, pv.y, pv.z, pv.w};
            float va[4] = {vv.x, vv.y, vv.z, vv.w};
            #pragma unroll
            for (int i = 0; i < 4; ++i)
                #pragma unroll
                for (int c = 0; c < 4; ++c)
                    ctx[i][c] = fmaf(pa[i], va[c], ctx[i][c]);
        }
    }

    // Write ctx: [s][b][head*64+d]
    const int b = m >> 4;
    const int h = m & 15;
    #pragma unroll
    for (int i = 0; i < 4; ++i) {
        size_t off = ((size_t)(q0 + ty * 4 + i) * BATCH + b) * HID + h * 64 + tx * 4;
        float4 v = make_float4(ctx[i][0], ctx[i][1], ctx[i][2], ctx[i][3]);
        *(float4*)(ctx_out + off) = v;
    }
}

// ---------------------------------------------------------------------------
extern "C" void kernel_launch(void* const* d_in, const int* in_sizes, int n_in,
                              void* d_out, int out_size)
{
    const float* hidden = (const float*)d_in[0];   // [S][B][H]
    const float* W      = (const float*)d_in[1];   // [3H][H]
    const float* bias   = (const float*)d_in[2];   // [3H]

    float* ctx_out   = (float*)d_out;                              // [S][B][H]
    float* score_out = ctx_out + (size_t)S_LEN * BATCH * HID;      // [M][S][S]

    dim3 g1(N_DIM / 128, M_DIM / 128);
    qkv_gemm_kernel<<<g1, 256>>>(hidden, W, bias);

    const int attn_smem = (4 * 64 * 68 + 128) * (int)sizeof(float);  // 70144 B
    cudaFuncSetAttribute(attn_kernel, cudaFuncAttributeMaxDynamicSharedMemorySize,
                         attn_smem);
    dim3 g2(S_LEN / 64, MHEADS);
    attn_kernel<<<g2, 256, attn_smem>>>(ctx_out, score_out);
}